// round 17
// baseline (speedup 1.0000x reference)
#include <cuda_runtime.h>
#include <cstdint>

// Problem constants
#define NB      4
#define NN      2048
#define PP      2096128            // NN*(NN-1)/2
#define TOTALF  (NB*PP)            // 8384512 flat pair slots per output row
#define RPG     32                 // rows per group (lane = row)
#define SPB     64                 // groups per batch
#define NGRP    (NB * SPB)         // 256 groups
#define CPGRP   (RPG * 64)         // 2048 chunk slots per group (abs j-chunks)
#define THREADS 256
#define FULL    0xffffffffu

// d2 <= 25.0f + 1ulp  <=>  sqrtf(d2) <= 5.0f (correctly rounded sqrt)
#define THR_BITS 0x41C80001u
#define NEG1F    0xBF800000        // -1.0f bits

#define FILLB   2048               // fill blocks inside combo kernel

// Scratch (__device__ globals; no allocations allowed)
__device__ unsigned g_mask[NGRP * CPGRP];   // 2 MB chunk validity bitmasks
__device__ int      g_soff[NGRP * CPGRP];   // 2 MB intra-group chunk offsets
__device__ int      g_gcnt[NGRP];
__device__ int      g_goff[NGRP];
__device__ int      g_total;

// ---------------------------------------------------------------------------
// K1: count — lane-per-row transposed mask build. Warp w streams absolute-j
// segment [256w, 256w+256); lane owns row r0+lane; masks accumulate in
// registers, one conflict-free STS per 32 j. No ballots, no sentinels.
// ---------------------------------------------------------------------------
__global__ void __launch_bounds__(THREADS) count_kernel(const float* __restrict__ x) {
    __shared__ float sx[NN];
    __shared__ float sy[NN];
    __shared__ float sz[NN];
    __shared__ unsigned smaskT[RPG * 65];   // row-major, 65-padded (bank-safe)
    __shared__ int wtot[8];
    __shared__ int wexc[8];

    const int gi = blockIdx.x;              // group = 32 consecutive rows
    const int b  = gi >> 6;
    const int r0 = (gi & 63) << 5;
    const int t  = threadIdx.x;
    const int w  = t >> 5;
    const int lane = t & 31;
    const float* xb = x + (size_t)b * NN * 3;

    for (int idx = t; idx < NN * 3; idx += THREADS) {
        float v = xb[idx];
        int pt = idx / 3, c3 = idx - 3 * pt;
        if (c3 == 0) sx[pt] = v; else if (c3 == 1) sy[pt] = v; else sz[pt] = v;
    }
    for (int idx = t; idx < RPG * 65; idx += THREADS) smaskT[idx] = 0;
    __syncthreads();

    const float thr = __uint_as_float(THR_BITS);
    const int i  = r0 + lane;               // this lane's row
    const float xi = sx[i], yi = sy[i], zi = sz[i];
    const int jbase = w << 8;               // warp's absolute-j segment

    if (jbase + 255 > r0) {                 // segment has any j > smallest row
        #pragma unroll
        for (int c8 = 0; c8 < 8; c8++) {
            const int cidx = (jbase >> 5) + c8;
            unsigned m = 0;
            #pragma unroll
            for (int e = 0; e < 32; e++) {
                const int j = (cidx << 5) + e;
                float dx = __fsub_rn(xi, sx[j]);
                float dy = __fsub_rn(yi, sy[j]);
                float dz = __fsub_rn(zi, sz[j]);
                float d2 = __fadd_rn(__fadd_rn(__fmul_rn(dx, dx), __fmul_rn(dy, dy)),
                                     __fmul_rn(dz, dz));
                if (d2 <= thr && j > i) m |= (1u << e);
            }
            smaskT[lane * 65 + cidx] = m;
        }
    }
    __syncthreads();

    // block scan over 2048 chunk popcounts (8 per thread, shfl-based)
    unsigned mk[8];
    int pc[8];
    const int rr = t >> 3;                  // row handled by this thread
    const int c0 = (t & 7) * 8;             // first chunk col
    int p = 0;
    #pragma unroll
    for (int e = 0; e < 8; e++) {
        mk[e] = smaskT[rr * 65 + c0 + e];
        pc[e] = __popc(mk[e]);
        p += pc[e];
    }
    int inc = p;
    #pragma unroll
    for (int d = 1; d < 32; d <<= 1) {
        int v = __shfl_up_sync(FULL, inc, d);
        if (lane >= d) inc += v;
    }
    if (lane == 31) wtot[w] = inc;
    __syncthreads();
    if (t < 32) {
        int vw = (lane < 8) ? wtot[lane] : 0;
        int winc = vw;
        #pragma unroll
        for (int d = 1; d < 8; d <<= 1) {
            int v = __shfl_up_sync(FULL, winc, d);
            if (lane >= d) winc += v;
        }
        if (lane < 8) wexc[lane] = winc - vw;
        if (lane == 7) g_gcnt[gi] = winc;
    }
    __syncthreads();

    // dump masks + running intra-group offsets (chunk order = (r, c) ascending)
    int run = wexc[w] + (inc - p);
    unsigned* gm = &g_mask[gi * CPGRP + 8 * t];
    int*      go = &g_soff[gi * CPGRP + 8 * t];
    #pragma unroll
    for (int e = 0; e < 8; e++) {
        gm[e] = mk[e];
        go[e] = run;
        run += pc[e];
    }
}

// ---------------------------------------------------------------------------
// K2: exclusive scan of 256 group counts — one block, shfl-based
// ---------------------------------------------------------------------------
__global__ void __launch_bounds__(256) scan_kernel() {
    __shared__ int wsum[8];
    const int t = threadIdx.x;
    const int w = t >> 5;
    const int lane = t & 31;

    int c = g_gcnt[t];
    int inc = c;
    #pragma unroll
    for (int d = 1; d < 32; d <<= 1) {
        int v = __shfl_up_sync(FULL, inc, d);
        if (lane >= d) inc += v;
    }
    if (lane == 31) wsum[w] = inc;
    __syncthreads();
    if (t < 32) {
        int vw = (lane < 8) ? wsum[lane] : 0;
        int winc = vw;
        #pragma unroll
        for (int d = 1; d < 8; d <<= 1) {
            int v = __shfl_up_sync(FULL, winc, d);
            if (lane >= d) winc += v;
        }
        if (lane < 8) wsum[lane] = winc - vw;
    }
    __syncthreads();
    g_goff[t] = wsum[w] + inc - c;
    if (t == 255) g_total = wsum[w] + inc;
}

// ---------------------------------------------------------------------------
// K3: combo — fill blocks write -1.0f over the invalid tail [total, TOTALF)
// of both rows; scatter blocks (one per group) write edges in [0, total).
// ---------------------------------------------------------------------------
__global__ void __launch_bounds__(256) combo_kernel(float* __restrict__ out) {
    const int t = threadIdx.x;

    if (blockIdx.x < FILLB) {
        // ---- fill role: grid-stride over int4 vectors, tail only
        const int total = g_total;
        const int NV = 2 * TOTALF / 4;       // TOTALF % 4 == 0: no row straddle
        int4 mm; mm.x = mm.y = mm.z = mm.w = NEG1F;
        int v = blockIdx.x * 256 + t;
        #pragma unroll
        for (int it = 0; it < 8; it++) {
            if (v < NV) {
                const int q0 = v * 4;
                const int local = (q0 < TOTALF) ? q0 : q0 - TOTALF;
                if (local >= total) {
                    reinterpret_cast<int4*>(out)[v] = mm;
                } else if (local + 4 > total) {
                    #pragma unroll
                    for (int e = 0; e < 4; e++)
                        if (local + e >= total) out[q0 + e] = -1.0f;
                }
            }
            v += FILLB * 256;
        }
        return;
    }

    // ---- scatter role: one block per group; wide loads, local bit-iterate
    const int gi = blockIdx.x - FILLB;
    const int b  = gi >> 6;
    const int r0 = (gi & 63) << 5;
    const int base = g_goff[gi];
    const int bofs = b * NN;
    float* out0 = out;
    float* out1 = out + TOTALF;

    const uint4 mv0 = reinterpret_cast<const uint4*>(&g_mask[gi * CPGRP + 8 * t])[0];
    const uint4 mv1 = reinterpret_cast<const uint4*>(&g_mask[gi * CPGRP + 8 * t])[1];
    const int4  ov0 = reinterpret_cast<const int4*>(&g_soff[gi * CPGRP + 8 * t])[0];
    const int4  ov1 = reinterpret_cast<const int4*>(&g_soff[gi * CPGRP + 8 * t])[1];
    const unsigned ma[8] = {mv0.x, mv0.y, mv0.z, mv0.w, mv1.x, mv1.y, mv1.z, mv1.w};
    const int      oa[8] = {ov0.x, ov0.y, ov0.z, ov0.w, ov1.x, ov1.y, ov1.z, ov1.w};

    #pragma unroll
    for (int e = 0; e < 8; e++) {
        unsigned m = ma[e];
        if (!m) continue;
        int off = base + oa[e];
        const int ch = 8 * t + e;
        const int rr = ch >> 6;              // row within group
        const int c  = ch & 63;              // absolute j-chunk
        const float fi = (float)(bofs + r0 + rr);
        const int jb = bofs + (c << 5);      // absolute j base
        while (m) {
            int bit = __ffs(m) - 1;
            m &= m - 1;
            out0[off] = fi;
            out1[off] = (float)(jb + bit);
            off++;
        }
    }
}

extern "C" void kernel_launch(void* const* d_in, const int* in_sizes, int n_in,
                              void* d_out, int out_size) {
    const float* x = (const float*)d_in[0];
    float* out = (float*)d_out;
    (void)in_sizes; (void)n_in; (void)out_size;

    count_kernel<<<NGRP, THREADS>>>(x);
    scan_kernel<<<1, 256>>>();
    combo_kernel<<<FILLB + NGRP, 256>>>(out);
}